// round 3
// baseline (speedup 1.0000x reference)
#include <cuda_runtime.h>

#define NROWS 2048
#define DFEAT 128
#define BLOCK 128
#define NWARP (BLOCK / 32)

__global__ __launch_bounds__(BLOCK, 12) void distance_sparse_kernel(
    const float* __restrict__ feats,
    const float* __restrict__ adj,
    float* __restrict__ out)
{
    const int i    = blockIdx.x;
    const int tid  = threadIdx.x;
    const int lane = tid & 31;
    const int warp = tid >> 5;
    const int sub  = lane & 15;   // sublane within 16-lane group
    const int grp  = lane >> 4;   // group 0/1: one column per group

    __shared__ unsigned short nzidx[NROWS];  // 4 KB
    __shared__ float          evals[NROWS];  // 8 KB (aligned with nzidx)
    __shared__ int   cnt;
    __shared__ float rowsum;

    // ---- issue adj-row loads first (DRAM latency is the long pole) ----
    const float4* arow4 = reinterpret_cast<const float4*>(adj + (size_t)i * NROWS);
    float4 a[4];
    #pragma unroll
    for (int c = 0; c < 4; c++) a[c] = arow4[tid + c * BLOCK];

    // fi: this lane's 2 float4 slices (sub + 16t)
    const float4* fi4p = reinterpret_cast<const float4*>(feats + (size_t)i * DFEAT);
    const float4 fi0 = fi4p[sub];
    const float4 fi1 = fi4p[sub + 16];

    if (tid == 0) { cnt = 0; rowsum = 0.0f; }
    __syncthreads();

    // ---- Phase 1: ballot-compact nonzero columns ----
    const unsigned lt = (1u << lane) - 1u;
    #pragma unroll
    for (int c = 0; c < 4; c++) {
        const float4 av = a[c];
        const int t = tid + c * BLOCK;
        const unsigned b0 = __ballot_sync(0xffffffffu, av.x != 0.0f);
        const unsigned b1 = __ballot_sync(0xffffffffu, av.y != 0.0f);
        const unsigned b2 = __ballot_sync(0xffffffffu, av.z != 0.0f);
        const unsigned b3 = __ballot_sync(0xffffffffu, av.w != 0.0f);
        const int c0 = __popc(b0), c1 = __popc(b1), c2 = __popc(b2), c3 = __popc(b3);
        int base = 0;
        if (lane == 0) base = atomicAdd(&cnt, c0 + c1 + c2 + c3);
        base = __shfl_sync(0xffffffffu, base, 0);
        const int col = t * 4;
        if (av.x != 0.0f) nzidx[base + __popc(b0 & lt)]                = (unsigned short)(col);
        if (av.y != 0.0f) nzidx[base + c0 + __popc(b1 & lt)]           = (unsigned short)(col + 1);
        if (av.z != 0.0f) nzidx[base + c0 + c1 + __popc(b2 & lt)]      = (unsigned short)(col + 2);
        if (av.w != 0.0f) nzidx[base + c0 + c1 + c2 + __popc(b3 & lt)] = (unsigned short)(col + 3);
    }
    __syncthreads();
    const int m = cnt;

    // ---- zero-fill output row now; fire-and-forget, overlapped with phase 2.
    //      Ordered before the scatter by the __syncthreads below. ----
    float4* orow4 = reinterpret_cast<float4*>(out + (size_t)i * NROWS);
    const float4 z = make_float4(0.f, 0.f, 0.f, 0.f);
    #pragma unroll
    for (int c = 0; c < 4; c++) orow4[tid + c * BLOCK] = z;

    // ---- Phase 2: 2 columns per warp per pass, 2x unrolled (4 independent chains) ----
    float wsum = 0.0f;
    for (int k2 = warp; k2 * 2 < m; k2 += 2 * NWARP) {
        const int  idxA = k2 * 2 + grp;
        const int  idxB = (k2 + NWARP) * 2 + grp;
        const bool actA = idxA < m;
        const bool actB = idxB < m;
        const int  jA = actA ? (int)nzidx[idxA] : 0;
        const int  jB = actB ? (int)nzidx[idxB] : 0;
        const float4* fjA = reinterpret_cast<const float4*>(feats + (size_t)jA * DFEAT);
        const float4* fjB = reinterpret_cast<const float4*>(feats + (size_t)jB * DFEAT);
        const float4 a0 = fjA[sub], a1 = fjA[sub + 16];
        const float4 b0 = fjB[sub], b1 = fjB[sub + 16];

        float sA = fabsf(fi0.x - a0.x) + fabsf(fi0.y - a0.y)
                 + fabsf(fi0.z - a0.z) + fabsf(fi0.w - a0.w)
                 + fabsf(fi1.x - a1.x) + fabsf(fi1.y - a1.y)
                 + fabsf(fi1.z - a1.z) + fabsf(fi1.w - a1.w);
        float sB = fabsf(fi0.x - b0.x) + fabsf(fi0.y - b0.y)
                 + fabsf(fi0.z - b0.z) + fabsf(fi0.w - b0.w)
                 + fabsf(fi1.x - b1.x) + fabsf(fi1.y - b1.y)
                 + fabsf(fi1.z - b1.z) + fabsf(fi1.w - b1.w);

        #pragma unroll
        for (int o = 8; o >= 1; o >>= 1) {
            sA += __shfl_xor_sync(0xffffffffu, sA, o);
            sB += __shfl_xor_sync(0xffffffffu, sB, o);
        }
        if (sub == 0) {
            if (actA) { const float e = __expf(-0.01f * sA); evals[idxA] = e; wsum += e; }
            if (actB) { const float e = __expf(-0.01f * sB); evals[idxB] = e; wsum += e; }
        }
    }
    // combine the two group leaders (lanes 0 and 16)
    wsum += __shfl_xor_sync(0xffffffffu, wsum, 16);
    if (lane == 0 && wsum != 0.0f) atomicAdd(&rowsum, wsum);
    __syncthreads();   // also orders the zero-fill stores before the scatter

    // ---- Phase 3: normalize + scatter the ~m nonzeros ----
    const float inv = 1.0f / fmaxf(rowsum, 1e-12f);
    float* orow = out + (size_t)i * NROWS;
    for (int t = tid; t < m; t += BLOCK)
        orow[nzidx[t]] = evals[t] * inv;
}

extern "C" void kernel_launch(void* const* d_in, const int* in_sizes, int n_in,
                              void* d_out, int out_size)
{
    const float* feats = (const float*)d_in[0];
    const float* adj   = (const float*)d_in[1];
    float* out         = (float*)d_out;
    distance_sparse_kernel<<<NROWS, BLOCK>>>(feats, adj, out);
}